// round 16
// baseline (speedup 1.0000x reference)
#include <cuda_runtime.h>
#include <cuda_bf16.h>
#include <cstdint>

#define BSZ 4
#define CCH 128
#define LL  4096
#define DDIM 64
#define BM  64
#define BN  64

// bf16 q/k/v, token-major, packed bf16x2 (d-pairs)
__device__ uint32_t g_q[BSZ * LL * 32];
__device__ uint32_t g_k[BSZ * LL * 32];
__device__ uint32_t g_v[BSZ * LL * 32];
// key-split partials: [b][rowtile][kh] x (64 rows x 64 d) fp32, and row sums
__device__ float g_po[BSZ * 64 * 2 * 4096];
__device__ float g_pl[BSZ * 64 * 2 * 64];

__device__ __forceinline__ uint32_t pack_bf16(float lo, float hi) {
    uint32_t r;
    asm("cvt.rn.bf16x2.f32 %0, %1, %2;" : "=r"(r) : "f"(hi), "f"(lo));
    return r;
}
__device__ __forceinline__ uint32_t smem_u32(const void* p) {
    uint32_t a;
    asm("{ .reg .u64 t; cvta.to.shared.u64 t, %1; cvt.u32.u64 %0, t; }" : "=r"(a) : "l"(p));
    return a;
}
__device__ __forceinline__ float ex2f(float x) {
    float r; asm("ex2.approx.f32 %0, %1;" : "=f"(r) : "f"(x)); return r;
}
__device__ __forceinline__ void mma16(float* c,
    uint32_t a0, uint32_t a1, uint32_t a2, uint32_t a3, uint32_t b0, uint32_t b1)
{
    asm volatile("mma.sync.aligned.m16n8k16.row.col.f32.bf16.bf16.f32 "
        "{%0,%1,%2,%3}, {%4,%5,%6,%7}, {%8,%9}, {%0,%1,%2,%3};"
        : "+f"(c[0]), "+f"(c[1]), "+f"(c[2]), "+f"(c[3])
        : "r"(a0), "r"(a1), "r"(a2), "r"(a3), "r"(b0), "r"(b1));
}
__device__ __forceinline__ void ldm4(uint32_t* r, uint32_t addr) {
    asm volatile("ldmatrix.sync.aligned.m8n8.x4.shared.b16 {%0,%1,%2,%3}, [%4];"
        : "=r"(r[0]), "=r"(r[1]), "=r"(r[2]), "=r"(r[3]) : "r"(addr));
}
__device__ __forceinline__ void ldm4t(uint32_t* r, uint32_t addr) {
    asm volatile("ldmatrix.sync.aligned.m8n8.x4.trans.shared.b16 {%0,%1,%2,%3}, [%4];"
        : "=r"(r[0]), "=r"(r[1]), "=r"(r[2]), "=r"(r[3]) : "r"(addr));
}
__device__ __forceinline__ void cp16(uint32_t dst, const void* src) {
    asm volatile("cp.async.cg.shared.global [%0], [%1], 16;"
                 :: "r"(dst), "l"(src) : "memory");
}
#define CP_COMMIT() asm volatile("cp.async.commit_group;" ::: "memory")

// =================== QKV via bf16 mma (x split hi+lo) =======================
#define XR 272
#define SW_W   0
#define SW_B   52224
#define SW_XH  52992
#define SW_XL  70400
#define SW_X32 87808
#define QKV_SMEM 105216

__global__ __launch_bounds__(256, 2) void qkv_kernel(
    const float* __restrict__ inpt,
    const float* __restrict__ Wq, const float* __restrict__ bq,
    const float* __restrict__ Wk, const float* __restrict__ bk,
    const float* __restrict__ Wv, const float* __restrict__ bv)
{
    extern __shared__ char sq[];
    const uint32_t sb = smem_u32(sq);
    const int tid = threadIdx.x, w = tid >> 5, lane = tid & 31;
    const int g = lane >> 2, qd = lane & 3;
    const int wr = w & 3, wc = w >> 2;
    const int b = blockIdx.y, l0 = blockIdx.x * 64;

    {
        const float* Wsrc[3] = {Wq, Wk, Wv};
        #pragma unroll
        for (int i = 0; i < 24; i++) {
            int idx = tid + i * 256;
            int r = idx >> 5, c4 = idx & 31;
            const float4 v = *(const float4*)(Wsrc[r >> 6] + (r & 63) * CCH + c4 * 4);
            *(uint2*)(sq + SW_W + r * XR + c4 * 8) =
                make_uint2(pack_bf16(v.x, v.y), pack_bf16(v.z, v.w));
        }
        if (tid < 192) {
            const float* bsrc[3] = {bq, bk, bv};
            ((float*)(sq + SW_B))[tid] = bsrc[tid >> 6][tid & 63];
        }
    }

    #pragma unroll
    for (int h = 0; h < 2; h++) {
        __syncthreads();
        const float* src = inpt + ((size_t)b * CCH + h * 64) * LL + l0;
        #pragma unroll
        for (int i = 0; i < 4; i++) {
            int idx = tid + i * 256;
            int c = idx >> 4, j4 = idx & 15;
            *(float4*)(sq + SW_X32 + (c * 68 + j4 * 4) * 4) =
                *(const float4*)(src + (size_t)c * LL + j4 * 4);
        }
        __syncthreads();
        const int j = tid & 63, q4 = tid >> 6;
        const float* x32 = (const float*)(sq + SW_X32);
        uint32_t hi[8], lo[8];
        #pragma unroll
        for (int i2 = 0; i2 < 8; i2++) {
            float a  = x32[(q4 * 16 + 2 * i2) * 68 + j];
            float b2 = x32[(q4 * 16 + 2 * i2 + 1) * 68 + j];
            hi[i2] = pack_bf16(a, b2);
            float ah = __bfloat162float(__float2bfloat16(a));
            float bh = __bfloat162float(__float2bfloat16(b2));
            lo[i2] = pack_bf16(a - ah, b2 - bh);
        }
        int off = j * XR + h * 128 + q4 * 32;
        *(uint4*)(sq + SW_XH + off)      = make_uint4(hi[0], hi[1], hi[2], hi[3]);
        *(uint4*)(sq + SW_XH + off + 16) = make_uint4(hi[4], hi[5], hi[6], hi[7]);
        *(uint4*)(sq + SW_XL + off)      = make_uint4(lo[0], lo[1], lo[2], lo[3]);
        *(uint4*)(sq + SW_XL + off + 16) = make_uint4(lo[4], lo[5], lo[6], lo[7]);
    }
    __syncthreads();

    float acc[12][4];
    #pragma unroll
    for (int i = 0; i < 12; i++) { acc[i][0]=0.f; acc[i][1]=0.f; acc[i][2]=0.f; acc[i][3]=0.f; }

    const uint32_t arow = (uint32_t)(wr * 16 + ((lane >> 3) & 1) * 8 + (lane & 7));
    const uint32_t brow = (uint32_t)(wc * 96 + (lane >> 4) * 8 + (lane & 7));
    #pragma unroll
    for (int kk = 0; kk < 8; kk++) {
        uint32_t ah[4], al[4], bw[6][4];
        uint32_t aaddr = sb + SW_XH + arow * XR + kk * 32 + (lane >> 4) * 16;
        ldm4(ah, aaddr);
        ldm4(al, aaddr + (SW_XL - SW_XH));
        #pragma unroll
        for (int hh = 0; hh < 6; hh++)
            ldm4(bw[hh], sb + SW_W + (brow + hh * 16) * XR + kk * 32 + ((lane >> 3) & 1) * 16);
        #pragma unroll
        for (int nb = 0; nb < 12; nb++) {
            uint32_t b0 = bw[nb >> 1][(nb & 1) * 2], b1 = bw[nb >> 1][(nb & 1) * 2 + 1];
            mma16(acc[nb], ah[0], ah[1], ah[2], ah[3], b0, b1);
            mma16(acc[nb], al[0], al[1], al[2], al[3], b0, b1);
        }
    }

    {
        const float* bias = (const float*)(sq + SW_B);
        uint32_t* outs[3] = {g_q, g_k, g_v};
        const int token0 = l0 + wr * 16 + g;
        #pragma unroll
        for (int nb = 0; nb < 12; nb++) {
            int n = wc * 96 + nb * 8 + 2 * qd;
            float2 bb = *(const float2*)(bias + n);
            uint32_t* op = outs[n >> 6];
            int d = n & 63;
            size_t base = ((size_t)(b * LL + token0)) * 32 + (d >> 1);
            op[base]          = pack_bf16(acc[nb][0] + bb.x, acc[nb][1] + bb.y);
            op[base + 8 * 32] = pack_bf16(acc[nb][2] + bb.x, acc[nb][3] + bb.y);
        }
    }
}

// ===== attention partials: grid (64 rowtiles, BSZ*2 key-halves), 32 tiles ===
#define RB 144
#define A_Q   0
#define A_KVB 9216            // 3 bufs of (K 9216 + V 9216) -> ends 64512
#define A_LS  64512
#define ASMEM 65024
#define P_O0  9216            // overlays inside dead ring
#define P_O1  26624

__global__ __launch_bounds__(256, 3) void attn_part_kernel()
{
    extern __shared__ char sm[];
    const uint32_t sb = smem_u32(sm);
    const int tid = threadIdx.x, w = tid >> 5, lane = tid & 31;
    const int wr = w & 3, wc = w >> 2;
    const int g = lane >> 2, qd = lane & 3;
    const int rt = blockIdx.x, bb = blockIdx.y >> 1, kh = blockIdx.y & 1;
    const int r0 = rt * BM, key0 = kh * 2048;
    const float SCALE = 0.18033688011112042f;

    // stage Q
    {
        #pragma unroll
        for (int i = 0; i < 2; i++) {
            int idx = tid + i * 256, row = idx >> 3, ch = idx & 7;
            *(uint4*)(sm + A_Q + row * RB + ch * 16) =
                *(const uint4*)(g_q + ((size_t)(bb * LL + r0 + row)) * 32 + ch * 4);
        }
    }
    // prologue KV stage -> buf 0
    {
        int row = tid >> 2, ch = tid & 3;
        const uint32_t* ks = g_k + ((size_t)(bb * LL + key0)) * 32;
        const uint32_t* vs = g_v + ((size_t)(bb * LL + key0)) * 32;
        #pragma unroll
        for (int i = 0; i < 2; i++) {
            cp16(sb + A_KVB + row * RB + (ch + 4 * i) * 16, ks + (size_t)row * 32 + (ch + 4 * i) * 4);
            cp16(sb + A_KVB + 9216 + row * RB + (ch + 4 * i) * 16, vs + (size_t)row * 32 + (ch + 4 * i) * 4);
        }
        CP_COMMIT();
    }
    __syncthreads();

    uint32_t qf[4][4];
    {
        uint32_t qrow = (uint32_t)(wr * 16 + ((lane >> 3) & 1) * 8 + (lane & 7));
        #pragma unroll
        for (int kk = 0; kk < 4; kk++)
            ldm4(qf[kk], sb + A_Q + qrow * RB + kk * 32 + (lane >> 4) * 16);
    }

    float o[8][4];
    #pragma unroll
    for (int i = 0; i < 8; i++) { o[i][0]=0.f; o[i][1]=0.f; o[i][2]=0.f; o[i][3]=0.f; }
    float slo = 0.f, shi = 0.f;

    const uint32_t krow = (uint32_t)(wc * 32 + (lane >> 4) * 8 + (lane & 7)) * RB
                        + ((lane >> 3) & 1) * 16;
    const uint32_t vrow = (uint32_t)(wc * 32 + ((lane >> 3) & 1) * 8 + (lane & 7)) * RB
                        + (lane >> 4) * 16;

    for (int kt = 0; kt < 32; kt++) {
        if (kt + 1 < 32) {
            uint32_t dst = sb + A_KVB + ((kt + 1) % 3) * 18432;
            int row = tid >> 2, ch = tid & 3;
            const uint32_t* ks = g_k + ((size_t)(bb * LL + key0 + (kt + 1) * BN)) * 32;
            const uint32_t* vs = g_v + ((size_t)(bb * LL + key0 + (kt + 1) * BN)) * 32;
            #pragma unroll
            for (int i = 0; i < 2; i++) {
                cp16(dst + row * RB + (ch + 4 * i) * 16, ks + (size_t)row * 32 + (ch + 4 * i) * 4);
                cp16(dst + 9216 + row * RB + (ch + 4 * i) * 16, vs + (size_t)row * 32 + (ch + 4 * i) * 4);
            }
            CP_COMMIT();
            asm volatile("cp.async.wait_group 1;" ::: "memory");
        } else {
            asm volatile("cp.async.wait_group 0;" ::: "memory");
        }
        __syncthreads();   // single barrier/tile (validated R14)

        const uint32_t bK = sb + A_KVB + (kt % 3) * 18432;
        const uint32_t bV = bK + 9216;

        // two 16-key chains, transient frags (80-reg body, validated R15)
        #pragma unroll
        for (int j = 0; j < 2; j++) {
            float s0[4] = {0.f, 0.f, 0.f, 0.f};
            float s1[4] = {0.f, 0.f, 0.f, 0.f};
            #pragma unroll
            for (int kk = 0; kk < 4; kk++) {
                uint32_t kf4[4];
                ldm4(kf4, bK + krow + j * 16 * RB + kk * 32);
                mma16(s0, qf[kk][0], qf[kk][1], qf[kk][2], qf[kk][3], kf4[0], kf4[1]);
                mma16(s1, qf[kk][0], qf[kk][1], qf[kk][2], qf[kk][3], kf4[2], kf4[3]);
            }
            float p0 = ex2f(s0[0] * SCALE), p1 = ex2f(s0[1] * SCALE);
            float p2 = ex2f(s0[2] * SCALE), p3 = ex2f(s0[3] * SCALE);
            float p4 = ex2f(s1[0] * SCALE), p5 = ex2f(s1[1] * SCALE);
            float p6 = ex2f(s1[2] * SCALE), p7 = ex2f(s1[3] * SCALE);
            slo += (p0 + p1) + (p4 + p5);
            shi += (p2 + p3) + (p6 + p7);
            uint32_t a0 = pack_bf16(p0, p1), a1 = pack_bf16(p2, p3);
            uint32_t a2 = pack_bf16(p4, p5), a3 = pack_bf16(p6, p7);
            #pragma unroll
            for (int hh = 0; hh < 4; hh++) {
                uint32_t vf4[4];
                ldm4t(vf4, bV + vrow + j * 16 * RB + hh * 32);
                mma16(o[2*hh],     a0, a1, a2, a3, vf4[0], vf4[1]);
                mma16(o[2*hh + 1], a0, a1, a2, a3, vf4[2], vf4[3]);
            }
        }
    }
    __syncthreads();   // ring dead

    // row sums
    slo += __shfl_xor_sync(0xFFFFFFFFu, slo, 1);
    slo += __shfl_xor_sync(0xFFFFFFFFu, slo, 2);
    shi += __shfl_xor_sync(0xFFFFFFFFu, shi, 1);
    shi += __shfl_xor_sync(0xFFFFFFFFu, shi, 2);
    if (qd == 0) {
        *(float*)(sm + A_LS + (wc * 64 + wr * 16 + g) * 4) = slo;
        *(float*)(sm + A_LS + (wc * 64 + wr * 16 + g + 8) * 4) = shi;
    }
    // partial O per wc into smem
    {
        float* sO = (float*)(sm + (wc ? P_O1 : P_O0));
        #pragma unroll
        for (int nb = 0; nb < 8; nb++) {
            int row0 = wr * 16 + g, d = nb * 8 + qd * 2;
            *(float2*)(sO + row0 * 68 + d)       = make_float2(o[nb][0], o[nb][1]);
            *(float2*)(sO + (row0 + 8) * 68 + d) = make_float2(o[nb][2], o[nb][3]);
        }
    }
    __syncthreads();

    // combine wc halves, write unnormalized partial O + lsum to gmem
    {
        const float* ls = (const float*)(sm + A_LS);
        const float* O0 = (const float*)(sm + P_O0);
        const float* O1 = (const float*)(sm + P_O1);
        float* po = g_po + ((size_t)((bb * 64 + rt) * 2 + kh)) * 4096;
        int row = tid >> 2, dq = (tid & 3) * 16;
        #pragma unroll
        for (int i = 0; i < 4; i++) {
            int d = dq + 4 * i;
            float4 v;
            v.x = O0[row * 68 + d]     + O1[row * 68 + d];
            v.y = O0[row * 68 + d + 1] + O1[row * 68 + d + 1];
            v.z = O0[row * 68 + d + 2] + O1[row * 68 + d + 2];
            v.w = O0[row * 68 + d + 3] + O1[row * 68 + d + 3];
            *(float4*)(po + row * 64 + d) = v;
        }
        if (tid < 64)
            g_pl[((size_t)((bb * 64 + rt) * 2 + kh)) * 64 + tid] = ls[tid] + ls[64 + tid];
    }
}

// ===== combine: sum key-halves, normalize, out-proj + bias + residual =======
#define C_WO  0
#define C_CTX 18432           // 64*144 -> 27648
#define C_ZS  0               // 64*133*4 = 34048 (after sync, over WO/CTX)
#define CSMEM 34048

__global__ __launch_bounds__(256, 2) void combine_kernel(
    const float* __restrict__ inpt,
    const float* __restrict__ Wo,
    const float* __restrict__ bo,
    float* __restrict__ out)
{
    extern __shared__ char sm[];
    const uint32_t sb = smem_u32(sm);
    const int tid = threadIdx.x, w = tid >> 5, lane = tid & 31;
    const int wr = w & 3, wc = w >> 2;
    const int g = lane >> 2, qd = lane & 3;
    const int rt = blockIdx.x, bb = blockIdx.y;
    const int r0 = rt * BM;

    // stage Wo bf16
    {
        #pragma unroll
        for (int i = 0; i < 4; i++) {
            int idx = tid + i * 256, row = idx >> 3, ch = idx & 7;
            const float4 v0 = *(const float4*)(Wo + row * DDIM + ch * 8);
            const float4 v1 = *(const float4*)(Wo + row * DDIM + ch * 8 + 4);
            *(uint4*)(sm + C_WO + row * RB + ch * 16) =
                make_uint4(pack_bf16(v0.x, v0.y), pack_bf16(v0.z, v0.w),
                           pack_bf16(v1.x, v1.y), pack_bf16(v1.z, v1.w));
        }
    }
    // ctx = (po0 + po1) / (pl0 + pl1), bf16 into C_CTX
    {
        const float* po0 = g_po + ((size_t)(bb * 64 + rt)) * 2 * 4096;
        const float* po1 = po0 + 4096;
        const float* pl  = g_pl + ((size_t)(bb * 64 + rt)) * 128;
        int row = tid >> 2, dq = (tid & 3) * 16;
        float invl = 1.f / (pl[row] + pl[64 + row]);
        #pragma unroll
        for (int i = 0; i < 8; i++) {
            int d = dq + 2 * i;
            float c0 = (po0[row * 64 + d]     + po1[row * 64 + d]) * invl;
            float c1 = (po0[row * 64 + d + 1] + po1[row * 64 + d + 1]) * invl;
            *(uint32_t*)(sm + C_CTX + row * RB + d * 2) = pack_bf16(c0, c1);
        }
    }
    __syncthreads();

    // Z = ctx @ Wo^T
    float z[8][4];
    #pragma unroll
    for (int i = 0; i < 8; i++) { z[i][0]=0.f; z[i][1]=0.f; z[i][2]=0.f; z[i][3]=0.f; }
    {
        uint32_t qrow = (uint32_t)(wr * 16 + ((lane >> 3) & 1) * 8 + (lane & 7));
        uint32_t wrow = (uint32_t)(wc * 64 + (lane >> 4) * 8 + (lane & 7)) * RB
                      + ((lane >> 3) & 1) * 16;
        #pragma unroll
        for (int kk = 0; kk < 4; kk++) {
            uint32_t cf[4], wf[4][4];
            ldm4(cf, sb + C_CTX + qrow * RB + kk * 32 + (lane >> 4) * 16);
            #pragma unroll
            for (int hh = 0; hh < 4; hh++)
                ldm4(wf[hh], sb + C_WO + wrow + hh * 16 * RB + kk * 32);
            #pragma unroll
            for (int nb = 0; nb < 8; nb++)
                mma16(z[nb], cf[0], cf[1], cf[2], cf[3],
                      wf[nb >> 1][(nb & 1) * 2], wf[nb >> 1][(nb & 1) * 2 + 1]);
        }
    }
    __syncthreads();   // WO/CTX reads done before ZS overwrite

    {
        float* zs = (float*)(sm + C_ZS);
        #pragma unroll
        for (int nb = 0; nb < 8; nb++) {
            int c = wc * 64 + nb * 8 + qd * 2, row0 = wr * 16 + g;
            zs[row0 * 133 + c]           = z[nb][0];
            zs[row0 * 133 + c + 1]       = z[nb][1];
            zs[(row0 + 8) * 133 + c]     = z[nb][2];
            zs[(row0 + 8) * 133 + c + 1] = z[nb][3];
        }
    }
    __syncthreads();
    {
        const float* zs = (const float*)(sm + C_ZS);
        int srow = tid & 63, cbase = (tid >> 6) * 32;
        #pragma unroll 8
        for (int i = 0; i < 32; i++) {
            int c = cbase + i;
            size_t idx = ((size_t)(bb * CCH + c)) * LL + r0 + srow;
            out[idx] = inpt[idx] + bo[c] + zs[srow * 133 + c];
        }
    }
}

extern "C" void kernel_launch(void* const* d_in, const int* in_sizes, int n_in,
                              void* d_out, int out_size)
{
    const float* inpt = (const float*)d_in[0];
    const float* Wq = (const float*)d_in[1];
    const float* bq = (const float*)d_in[2];
    const float* Wk = (const float*)d_in[3];
    const float* bk = (const float*)d_in[4];
    const float* Wv = (const float*)d_in[5];
    const float* bv = (const float*)d_in[6];
    const float* Wo = (const float*)d_in[7];
    const float* bo = (const float*)d_in[8];
    float* out = (float*)d_out;

    cudaFuncSetAttribute(qkv_kernel, cudaFuncAttributeMaxDynamicSharedMemorySize, QKV_SMEM);
    cudaFuncSetAttribute(attn_part_kernel, cudaFuncAttributeMaxDynamicSharedMemorySize, ASMEM);
    cudaFuncSetAttribute(combine_kernel, cudaFuncAttributeMaxDynamicSharedMemorySize, CSMEM);

    dim3 g1(LL / 64, BSZ);
    qkv_kernel<<<g1, 256, QKV_SMEM>>>(inpt, Wq, bq, Wk, bk, Wv, bv);
    dim3 g2(LL / BM, BSZ * 2);
    attn_part_kernel<<<g2, 256, ASMEM>>>();
    dim3 g3(LL / BM, BSZ);
    combine_kernel<<<g3, 256, CSMEM>>>(inpt, Wo, bo, out);
}

// round 17
// speedup vs baseline: 1.1788x; 1.1788x over previous
#include <cuda_runtime.h>
#include <cuda_bf16.h>
#include <cuda_fp16.h>
#include <cstdint>

#define BSZ 4
#define CCH 128
#define LL  4096
#define DDIM 64
#define BM  64
#define BN  64
#define NT  (LL/BN)

// bf16 q/k/v, all token-major, packed bf16x2 (d-pairs); q pre-scaled by log2(e)/8
__device__ uint32_t g_q[BSZ * LL * 32];
__device__ uint32_t g_k[BSZ * LL * 32];
__device__ uint32_t g_v[BSZ * LL * 32];

__device__ __forceinline__ uint32_t pack_bf16(float lo, float hi) {
    uint32_t r;
    asm("cvt.rn.bf16x2.f32 %0, %1, %2;" : "=r"(r) : "f"(hi), "f"(lo));
    return r;
}
__device__ __forceinline__ uint32_t pack_f16(float lo, float hi) {
    uint32_t r;
    asm("cvt.rn.f16x2.f32 %0, %1, %2;" : "=r"(r) : "f"(hi), "f"(lo));
    return r;
}
__device__ __forceinline__ uint32_t smem_u32(const void* p) {
    uint32_t a;
    asm("{ .reg .u64 t; cvta.to.shared.u64 t, %1; cvt.u32.u64 %0, t; }" : "=r"(a) : "l"(p));
    return a;
}
__device__ __forceinline__ void mma16(float* c,
    uint32_t a0, uint32_t a1, uint32_t a2, uint32_t a3, uint32_t b0, uint32_t b1)
{
    asm volatile("mma.sync.aligned.m16n8k16.row.col.f32.bf16.bf16.f32 "
        "{%0,%1,%2,%3}, {%4,%5,%6,%7}, {%8,%9}, {%0,%1,%2,%3};"
        : "+f"(c[0]), "+f"(c[1]), "+f"(c[2]), "+f"(c[3])
        : "r"(a0), "r"(a1), "r"(a2), "r"(a3), "r"(b0), "r"(b1));
}
__device__ __forceinline__ void ldm4(uint32_t* r, uint32_t addr) {
    asm volatile("ldmatrix.sync.aligned.m8n8.x4.shared.b16 {%0,%1,%2,%3}, [%4];"
        : "=r"(r[0]), "=r"(r[1]), "=r"(r[2]), "=r"(r[3]) : "r"(addr));
}
__device__ __forceinline__ void ldm4t(uint32_t* r, uint32_t addr) {
    asm volatile("ldmatrix.sync.aligned.m8n8.x4.trans.shared.b16 {%0,%1,%2,%3}, [%4];"
        : "=r"(r[0]), "=r"(r[1]), "=r"(r[2]), "=r"(r[3]) : "r"(addr));
}
__device__ __forceinline__ void cp16(uint32_t dst, const void* src) {
    asm volatile("cp.async.cg.shared.global [%0], [%1], 16;"
                 :: "r"(dst), "l"(src) : "memory");
}
#define CP_COMMIT() asm volatile("cp.async.commit_group;" ::: "memory")

// =================== QKV via bf16 mma (x split hi+lo) =======================
#define XR 272
#define SW_W   0
#define SW_B   52224
#define SW_XH  52992
#define SW_XL  70400
#define SW_X32 87808
#define QKV_SMEM 105216

__global__ __launch_bounds__(256, 2) void qkv_kernel(
    const float* __restrict__ inpt,
    const float* __restrict__ Wq, const float* __restrict__ bq,
    const float* __restrict__ Wk, const float* __restrict__ bk,
    const float* __restrict__ Wv, const float* __restrict__ bv)
{
    extern __shared__ char sq[];
    const uint32_t sb = smem_u32(sq);
    const int tid = threadIdx.x, w = tid >> 5, lane = tid & 31;
    const int g = lane >> 2, qd = lane & 3;
    const int wr = w & 3, wc = w >> 2;
    const int b = blockIdx.y, l0 = blockIdx.x * 64;

    {
        const float* Wsrc[3] = {Wq, Wk, Wv};
        #pragma unroll
        for (int i = 0; i < 24; i++) {
            int idx = tid + i * 256;
            int r = idx >> 5, c4 = idx & 31;
            const float4 v = *(const float4*)(Wsrc[r >> 6] + (r & 63) * CCH + c4 * 4);
            *(uint2*)(sq + SW_W + r * XR + c4 * 8) =
                make_uint2(pack_bf16(v.x, v.y), pack_bf16(v.z, v.w));
        }
        if (tid < 192) {
            const float* bsrc[3] = {bq, bk, bv};
            ((float*)(sq + SW_B))[tid] = bsrc[tid >> 6][tid & 63];
        }
    }

    #pragma unroll
    for (int h = 0; h < 2; h++) {
        __syncthreads();
        const float* src = inpt + ((size_t)b * CCH + h * 64) * LL + l0;
        #pragma unroll
        for (int i = 0; i < 4; i++) {
            int idx = tid + i * 256;
            int c = idx >> 4, j4 = idx & 15;
            *(float4*)(sq + SW_X32 + (c * 68 + j4 * 4) * 4) =
                *(const float4*)(src + (size_t)c * LL + j4 * 4);
        }
        __syncthreads();
        const int j = tid & 63, q4 = tid >> 6;
        const float* x32 = (const float*)(sq + SW_X32);
        uint32_t hi[8], lo[8];
        #pragma unroll
        for (int i2 = 0; i2 < 8; i2++) {
            float a  = x32[(q4 * 16 + 2 * i2) * 68 + j];
            float b2 = x32[(q4 * 16 + 2 * i2 + 1) * 68 + j];
            hi[i2] = pack_bf16(a, b2);
            float ah = __bfloat162float(__float2bfloat16(a));
            float bh = __bfloat162float(__float2bfloat16(b2));
            lo[i2] = pack_bf16(a - ah, b2 - bh);
        }
        int off = j * XR + h * 128 + q4 * 32;
        *(uint4*)(sq + SW_XH + off)      = make_uint4(hi[0], hi[1], hi[2], hi[3]);
        *(uint4*)(sq + SW_XH + off + 16) = make_uint4(hi[4], hi[5], hi[6], hi[7]);
        *(uint4*)(sq + SW_XL + off)      = make_uint4(lo[0], lo[1], lo[2], lo[3]);
        *(uint4*)(sq + SW_XL + off + 16) = make_uint4(lo[4], lo[5], lo[6], lo[7]);
    }
    __syncthreads();

    float acc[12][4];
    #pragma unroll
    for (int i = 0; i < 12; i++) { acc[i][0]=0.f; acc[i][1]=0.f; acc[i][2]=0.f; acc[i][3]=0.f; }

    const uint32_t arow = (uint32_t)(wr * 16 + ((lane >> 3) & 1) * 8 + (lane & 7));
    const uint32_t brow = (uint32_t)(wc * 96 + (lane >> 4) * 8 + (lane & 7));
    #pragma unroll
    for (int kk = 0; kk < 8; kk++) {
        uint32_t ah[4], al[4], bw[6][4];
        uint32_t aaddr = sb + SW_XH + arow * XR + kk * 32 + (lane >> 4) * 16;
        ldm4(ah, aaddr);
        ldm4(al, aaddr + (SW_XL - SW_XH));
        #pragma unroll
        for (int hh = 0; hh < 6; hh++)
            ldm4(bw[hh], sb + SW_W + (brow + hh * 16) * XR + kk * 32 + ((lane >> 3) & 1) * 16);
        #pragma unroll
        for (int nb = 0; nb < 12; nb++) {
            uint32_t b0 = bw[nb >> 1][(nb & 1) * 2], b1 = bw[nb >> 1][(nb & 1) * 2 + 1];
            mma16(acc[nb], ah[0], ah[1], ah[2], ah[3], b0, b1);
            mma16(acc[nb], al[0], al[1], al[2], al[3], b0, b1);
        }
    }

    {
        const float* bias = (const float*)(sq + SW_B);
        uint32_t* outs[3] = {g_q, g_k, g_v};
        const int token0 = l0 + wr * 16 + g;
        #pragma unroll
        for (int nb = 0; nb < 12; nb++) {
            int n = wc * 96 + nb * 8 + 2 * qd;
            float2 bb = *(const float2*)(bias + n);
            uint32_t* op = outs[n >> 6];
            float sc = (n < 64) ? 0.18033688011112042f : 1.0f;  // q pre-scaled
            int d = n & 63;
            size_t base = ((size_t)(b * LL + token0)) * 32 + (d >> 1);
            op[base]          = pack_bf16((acc[nb][0] + bb.x) * sc, (acc[nb][1] + bb.y) * sc);
            op[base + 8 * 32] = pack_bf16((acc[nb][2] + bb.x) * sc, (acc[nb][3] + bb.y) * sc);
        }
    }
}

// ====== attention + fused out-proj (R14 base; f16x2 exp, q pre-scaled) ======
#define RB 144
#define A_Q   0
#define A_KVB 9216            // 3 bufs of (K 9216 + V 9216)
#define A_WO  64512           // 128*144
#define A_LS  82944
#define A_O0  9216
#define A_O1  26624
#define A_ZS  9216
#define ASMEM 83456

__global__ __launch_bounds__(256, 2) void attn_kernel(
    const float* __restrict__ inpt,
    const float* __restrict__ Wo,
    const float* __restrict__ bo,
    float* __restrict__ out)
{
    extern __shared__ char sm[];
    const uint32_t sb = smem_u32(sm);
    const int tid = threadIdx.x, w = tid >> 5, lane = tid & 31;
    const int wr = w & 3, wc = w >> 2;        // row-group / key-half
    const int g = lane >> 2, qd = lane & 3;
    const int bb = blockIdx.y, r0 = blockIdx.x * BM;

    // stage Q (64 rows x 64 bf16 = 128B/row)
    {
        #pragma unroll
        for (int i = 0; i < 2; i++) {
            int idx = tid + i * 256, row = idx >> 3, ch = idx & 7;
            *(uint4*)(sm + A_Q + row * RB + ch * 16) =
                *(const uint4*)(g_q + ((size_t)(bb * LL + r0 + row)) * 32 + ch * 4);
        }
    }
    // stage Wo bf16 (128 rows x 64)
    {
        #pragma unroll
        for (int i = 0; i < 4; i++) {
            int idx = tid + i * 256, row = idx >> 3, ch = idx & 7;
            const float4 v0 = *(const float4*)(Wo + row * DDIM + ch * 8);
            const float4 v1 = *(const float4*)(Wo + row * DDIM + ch * 8 + 4);
            *(uint4*)(sm + A_WO + row * RB + ch * 16) =
                make_uint4(pack_bf16(v0.x, v0.y), pack_bf16(v0.z, v0.w),
                           pack_bf16(v1.x, v1.y), pack_bf16(v1.z, v1.w));
        }
    }
    // prologue KV stage -> buf 0
    {
        int row = tid >> 2, ch = tid & 3;
        const uint32_t* ks = g_k + ((size_t)(bb * LL)) * 32;
        const uint32_t* vs = g_v + ((size_t)(bb * LL)) * 32;
        #pragma unroll
        for (int i = 0; i < 2; i++) {
            cp16(sb + A_KVB + row * RB + (ch + 4 * i) * 16, ks + (size_t)row * 32 + (ch + 4 * i) * 4);
            cp16(sb + A_KVB + 9216 + row * RB + (ch + 4 * i) * 16, vs + (size_t)row * 32 + (ch + 4 * i) * 4);
        }
        CP_COMMIT();
    }
    __syncthreads();

    // Q frags
    uint32_t qf[4][4];
    {
        uint32_t qrow = (uint32_t)(wr * 16 + ((lane >> 3) & 1) * 8 + (lane & 7));
        #pragma unroll
        for (int kk = 0; kk < 4; kk++)
            ldm4(qf[kk], sb + A_Q + qrow * RB + kk * 32 + (lane >> 4) * 16);
    }

    float o[8][4];
    #pragma unroll
    for (int i = 0; i < 8; i++) { o[i][0]=0.f; o[i][1]=0.f; o[i][2]=0.f; o[i][3]=0.f; }
    float slo = 0.f, shi = 0.f;

    const uint32_t krow = (uint32_t)(wc * 32 + (lane >> 4) * 8 + (lane & 7)) * RB
                        + ((lane >> 3) & 1) * 16;
    const uint32_t vrow = (uint32_t)(wc * 32 + ((lane >> 3) & 1) * 8 + (lane & 7)) * RB
                        + (lane >> 4) * 16;

    for (int kt = 0; kt < NT; kt++) {
        if (kt + 1 < NT) {   // prefetch into buf (kt+1)%3
            uint32_t dst = sb + A_KVB + ((kt + 1) % 3) * 18432;
            int row = tid >> 2, ch = tid & 3;
            const uint32_t* ks = g_k + ((size_t)(bb * LL + (kt + 1) * BN)) * 32;
            const uint32_t* vs = g_v + ((size_t)(bb * LL + (kt + 1) * BN)) * 32;
            #pragma unroll
            for (int i = 0; i < 2; i++) {
                cp16(dst + row * RB + (ch + 4 * i) * 16, ks + (size_t)row * 32 + (ch + 4 * i) * 4);
                cp16(dst + 9216 + row * RB + (ch + 4 * i) * 16, vs + (size_t)row * 32 + (ch + 4 * i) * 4);
            }
            CP_COMMIT();
            asm volatile("cp.async.wait_group 1;" ::: "memory");
        } else {
            asm volatile("cp.async.wait_group 0;" ::: "memory");
        }
        __syncthreads();   // single barrier per tile (validated R14)

        const uint32_t bK = sb + A_KVB + (kt % 3) * 18432;
        const uint32_t bV = bK + 9216;

        // K frags
        uint32_t kf[4][2][4];
        #pragma unroll
        for (int kk = 0; kk < 4; kk++)
            #pragma unroll
            for (int h = 0; h < 2; h++)
                ldm4(kf[kk][h], bK + krow + h * 16 * RB + kk * 32);

        // S = Q @ K^T (q pre-scaled by log2(e)/8)
        float s[4][4];
        #pragma unroll
        for (int i = 0; i < 4; i++) { s[i][0]=0.f; s[i][1]=0.f; s[i][2]=0.f; s[i][3]=0.f; }
        #pragma unroll
        for (int kk = 0; kk < 4; kk++)
            #pragma unroll
            for (int nb = 0; nb < 4; nb++)
                mma16(s[nb], qf[kk][0], qf[kk][1], qf[kk][2], qf[kk][3],
                      kf[kk][nb >> 1][(nb & 1) * 2], kf[kk][nb >> 1][(nb & 1) * 2 + 1]);

        // exp via ex2.approx.f16x2 (1 MUFU per 2 values); sums + P in fp32/bf16
        uint32_t pr[4][2];
        #pragma unroll
        for (int nb = 0; nb < 4; nb++) {
            uint32_t in0 = pack_f16(s[nb][0], s[nb][1]);
            uint32_t in1 = pack_f16(s[nb][2], s[nb][3]);
            uint32_t e0, e1;
            asm("ex2.approx.f16x2 %0, %1;" : "=r"(e0) : "r"(in0));
            asm("ex2.approx.f16x2 %0, %1;" : "=r"(e1) : "r"(in1));
            __half2 h0 = *reinterpret_cast<__half2*>(&e0);
            __half2 h1 = *reinterpret_cast<__half2*>(&e1);
            float p0 = __low2float(h0), p1 = __high2float(h0);
            float p2 = __low2float(h1), p3 = __high2float(h1);
            slo += p0 + p1; shi += p2 + p3;
            pr[nb][0] = pack_bf16(p0, p1);
            pr[nb][1] = pack_bf16(p2, p3);
        }

        // V frags (trans)
        uint32_t vf[2][4][4];
        #pragma unroll
        for (int j = 0; j < 2; j++)
            #pragma unroll
            for (int hh = 0; hh < 4; hh++)
                ldm4t(vf[j][hh], bV + vrow + j * 16 * RB + hh * 32);

        // O += P @ V
        #pragma unroll
        for (int j = 0; j < 2; j++) {
            uint32_t a0 = pr[2*j][0], a1 = pr[2*j][1];
            uint32_t a2 = pr[2*j+1][0], a3 = pr[2*j+1][1];
            #pragma unroll
            for (int nb = 0; nb < 8; nb++)
                mma16(o[nb], a0, a1, a2, a3,
                      vf[j][nb >> 1][(nb & 1) * 2], vf[j][nb >> 1][(nb & 1) * 2 + 1]);
        }
        // (no trailing barrier: 3-stage ring bounds skew; validated R14)
    }
    __syncthreads();   // all KV-buffer reads done before O0/O1 aliasing writes

    // quad-reduce row sums, publish per key-half
    slo += __shfl_xor_sync(0xFFFFFFFFu, slo, 1);
    slo += __shfl_xor_sync(0xFFFFFFFFu, slo, 2);
    shi += __shfl_xor_sync(0xFFFFFFFFu, shi, 1);
    shi += __shfl_xor_sync(0xFFFFFFFFu, shi, 2);
    if (qd == 0) {
        *(float*)(sm + A_LS + (wc * 64 + wr * 16 + g) * 4) = slo;
        *(float*)(sm + A_LS + (wc * 64 + wr * 16 + g + 8) * 4) = shi;
    }
    // partial O per key-half
    {
        float* sO = (float*)(sm + (wc ? A_O1 : A_O0));
        #pragma unroll
        for (int nb = 0; nb < 8; nb++) {
            int row0 = wr * 16 + g, d = nb * 8 + qd * 2;
            *(float2*)(sO + row0 * 68 + d)       = make_float2(o[nb][0], o[nb][1]);
            *(float2*)(sO + (row0 + 8) * 68 + d) = make_float2(o[nb][2], o[nb][3]);
        }
    }
    __syncthreads();

    // combine halves, normalize, bf16 ctx into A_Q
    {
        const float* ls = (const float*)(sm + A_LS);
        const float* O0 = (const float*)(sm + A_O0);
        const float* O1 = (const float*)(sm + A_O1);
        int row = tid >> 2, dq = (tid & 3) * 16;
        float invl = 1.f / (ls[row] + ls[64 + row]);
        #pragma unroll
        for (int i = 0; i < 8; i++) {
            int d = dq + 2 * i;
            float c0 = (O0[row * 68 + d] + O1[row * 68 + d]) * invl;
            float c1 = (O0[row * 68 + d + 1] + O1[row * 68 + d + 1]) * invl;
            *(uint32_t*)(sm + A_Q + row * RB + d * 2) = pack_bf16(c0, c1);
        }
    }
    __syncthreads();

    // Z = ctx @ Wo^T
    float z[8][4];
    #pragma unroll
    for (int i = 0; i < 8; i++) { z[i][0]=0.f; z[i][1]=0.f; z[i][2]=0.f; z[i][3]=0.f; }
    {
        uint32_t qrow = (uint32_t)(wr * 16 + ((lane >> 3) & 1) * 8 + (lane & 7));
        uint32_t wrow = (uint32_t)(wc * 64 + (lane >> 4) * 8 + (lane & 7)) * RB
                      + ((lane >> 3) & 1) * 16;
        #pragma unroll
        for (int kk = 0; kk < 4; kk++) {
            uint32_t cf[4], wf[4][4];
            ldm4(cf, sb + A_Q + qrow * RB + kk * 32 + (lane >> 4) * 16);
            #pragma unroll
            for (int hh = 0; hh < 4; hh++)
                ldm4(wf[hh], sb + A_WO + wrow + hh * 16 * RB + kk * 32);
            #pragma unroll
            for (int nb = 0; nb < 8; nb++)
                mma16(z[nb], cf[0], cf[1], cf[2], cf[3],
                      wf[nb >> 1][(nb & 1) * 2], wf[nb >> 1][(nb & 1) * 2 + 1]);
        }
    }
    __syncthreads();   // O0/O1 reads finished before zs overwrite

    // stage Z (stride 133), coalesced bias+residual store
    {
        float* zs = (float*)(sm + A_ZS);
        #pragma unroll
        for (int nb = 0; nb < 8; nb++) {
            int c = wc * 64 + nb * 8 + qd * 2, row0 = wr * 16 + g;
            zs[row0 * 133 + c]           = z[nb][0];
            zs[row0 * 133 + c + 1]       = z[nb][1];
            zs[(row0 + 8) * 133 + c]     = z[nb][2];
            zs[(row0 + 8) * 133 + c + 1] = z[nb][3];
        }
    }
    __syncthreads();
    {
        const float* zs = (const float*)(sm + A_ZS);
        int srow = tid & 63, cbase = (tid >> 6) * 32;
        #pragma unroll 8
        for (int i = 0; i < 32; i++) {
            int c = cbase + i;
            size_t idx = ((size_t)(bb * CCH + c)) * LL + r0 + srow;
            out[idx] = inpt[idx] + bo[c] + zs[srow * 133 + c];
        }
    }
}

extern "C" void kernel_launch(void* const* d_in, const int* in_sizes, int n_in,
                              void* d_out, int out_size)
{
    const float* inpt = (const float*)d_in[0];
    const float* Wq = (const float*)d_in[1];
    const float* bq = (const float*)d_in[2];
    const float* Wk = (const float*)d_in[3];
    const float* bk = (const float*)d_in[4];
    const float* Wv = (const float*)d_in[5];
    const float* bv = (const float*)d_in[6];
    const float* Wo = (const float*)d_in[7];
    const float* bo = (const float*)d_in[8];
    float* out = (float*)d_out;

    cudaFuncSetAttribute(qkv_kernel, cudaFuncAttributeMaxDynamicSharedMemorySize, QKV_SMEM);
    cudaFuncSetAttribute(attn_kernel, cudaFuncAttributeMaxDynamicSharedMemorySize, ASMEM);

    dim3 g1(LL / 64, BSZ);
    qkv_kernel<<<g1, 256, QKV_SMEM>>>(inpt, Wq, bq, Wk, bk, Wv, bv);
    dim3 g2(LL / BM, BSZ);
    attn_kernel<<<g2, 256, ASMEM>>>(inpt, Wo, bo, out);
}